// round 4
// baseline (speedup 1.0000x reference)
#include <cuda_runtime.h>
#include <cuda_bf16.h>
#include <cstdint>

// ---- problem constants ----
#define Bq   4
#define Tq   1024
#define Eq   512
#define Hq   8
#define HDq  64
#define NBq  5
#define VOC  32000
#define MROWS (Bq*Tq)          // 4096

// ---- scratch (device globals; no allocations allowed) ----
__device__ float g_h1 [MROWS*Eq];
__device__ float g_h2 [MROWS*Eq];
__device__ float g_hn [MROWS*Eq];
__device__ float g_k  [MROWS*Eq];
__device__ float g_q  [MROWS*Eq];
__device__ float g_mha[MROWS*Eq];
__device__ float g_wkr[NBq*Eq*Eq];
__device__ float g_wqr[NBq*Eq*Eq];

// ============================================================
// repack Wk/Wq: [NB,H,E,HD] -> [NB,E,H*HD]  (row-major B matrix)
// ============================================================
__global__ void repack_kernel(const float* __restrict__ in, float* __restrict__ out)
{
    int tid = blockIdx.x * blockDim.x + threadIdx.x;   // NB*H*E*16 threads
    if (tid >= NBq * Hq * Eq * 16) return;
    int o4 = tid & 15;
    int e  = (tid >> 4) & 511;
    int h  = (tid >> 13) & 7;
    int i  = tid >> 16;
    float4 v = *(const float4*)(in  + ((((size_t)i*Hq + h)*Eq + e)*HDq + o4*4));
    *(float4*)(out + (((size_t)i*Eq + e)*Eq + h*HDq + o4*4)) = v;
}

// ============================================================
// embedding: h[b,t,:] = tok_emb[x[b,t],:] + pos_emb[t,:]
// one block per token row, 128 threads, float4
// ============================================================
__global__ void embed_kernel(const int* __restrict__ x,
                             const float* __restrict__ tok,
                             const float* __restrict__ pos,
                             float* __restrict__ h)
{
    int row = blockIdx.x;              // b*T + t
    int t   = row & (Tq - 1);
    int idx = x[row];
    int tid = threadIdx.x;             // 0..127
    float4 a = ((const float4*)(tok + (size_t)idx * Eq))[tid];
    float4 p = ((const float4*)(pos + (size_t)t   * Eq))[tid];
    float4 o; o.x = a.x+p.x; o.y = a.y+p.y; o.z = a.z+p.z; o.w = a.w+p.w;
    ((float4*)(h + (size_t)row * Eq))[tid] = o;
}

// ============================================================
// layernorm: one block per row (512 floats), 128 threads
// ============================================================
__global__ void ln_kernel(const float* __restrict__ in,
                          const float* __restrict__ g,
                          const float* __restrict__ b,
                          float* __restrict__ out)
{
    int row = blockIdx.x, tid = threadIdx.x;
    float4 v = ((const float4*)(in + (size_t)row * Eq))[tid];
    float s  = v.x + v.y + v.z + v.w;
    float sq = v.x*v.x + v.y*v.y + v.z*v.z + v.w*v.w;
    #pragma unroll
    for (int o = 16; o; o >>= 1) {
        s  += __shfl_xor_sync(0xffffffffu, s,  o);
        sq += __shfl_xor_sync(0xffffffffu, sq, o);
    }
    __shared__ float sm[4], sm2[4];
    int wid = tid >> 5, lane = tid & 31;
    if (lane == 0) { sm[wid] = s; sm2[wid] = sq; }
    __syncthreads();
    s  = sm[0] + sm[1] + sm[2] + sm[3];
    sq = sm2[0] + sm2[1] + sm2[2] + sm2[3];
    float mu   = s * (1.0f / Eq);
    float var  = sq * (1.0f / Eq) - mu * mu;
    float rstd = rsqrtf(var + 1e-5f);
    float4 gv = ((const float4*)g)[tid];
    float4 bv = ((const float4*)b)[tid];
    float4 o;
    o.x = (v.x - mu) * rstd * gv.x + bv.x;
    o.y = (v.y - mu) * rstd * gv.y + bv.y;
    o.z = (v.z - mu) * rstd * gv.z + bv.z;
    o.w = (v.w - mu) * rstd * gv.w + bv.w;
    ((float4*)(out + (size_t)row * Eq))[tid] = o;
}

// ============================================================
// SGEMM: C[M,N] = A[M,K] @ B[K,N]  (+bias, +relu, +resid)
// 128x128 block tile, BK=8, 256 threads, 8x8 per thread
// Requires M%128==0, N%128==0, K%8==0, 16B-aligned pointers.
// epilogue: v = A@B (+bias[col]); if RELU v=max(v,0); if RESID v+=resid[r,c]
// ============================================================
template<bool BIAS, bool RELU, bool RESID>
__global__ __launch_bounds__(256) void sgemm(
    const float* __restrict__ A, const float* __restrict__ B,
    const float* __restrict__ bias, const float* __restrict__ resid,
    float* __restrict__ C, int M, int N, int K)
{
    __shared__ float As[8][128];
    __shared__ float Bs[8][128];
    int tid = threadIdx.x;
    int m0 = blockIdx.y * 128;
    int n0 = blockIdx.x * 128;
    int tx = tid & 15, ty = tid >> 4;

    int a_row = tid >> 1, a_kq = (tid & 1) * 4;
    int b_k   = tid >> 5, b_n  = (tid & 31) * 4;

    const float* Aptr = A + (size_t)(m0 + a_row) * K + a_kq;
    const float* Bptr = B + (size_t)b_k * N + n0 + b_n;

    float4 a_reg = *(const float4*)Aptr;
    float4 b_reg = *(const float4*)Bptr;

    float acc[8][8];
    #pragma unroll
    for (int i = 0; i < 8; i++)
        #pragma unroll
        for (int j = 0; j < 8; j++) acc[i][j] = 0.0f;

    int KT = K >> 3;
    for (int kt = 0; kt < KT; kt++) {
        As[a_kq + 0][a_row] = a_reg.x;
        As[a_kq + 1][a_row] = a_reg.y;
        As[a_kq + 2][a_row] = a_reg.z;
        As[a_kq + 3][a_row] = a_reg.w;
        *(float4*)&Bs[b_k][b_n] = b_reg;
        __syncthreads();
        if (kt + 1 < KT) {
            a_reg = *(const float4*)(Aptr + (size_t)(kt + 1) * 8);
            b_reg = *(const float4*)(Bptr + (size_t)(kt + 1) * 8 * N);
        }
        #pragma unroll
        for (int k = 0; k < 8; k++) {
            float4 a0 = *(const float4*)&As[k][ty * 4];
            float4 a1 = *(const float4*)&As[k][64 + ty * 4];
            float4 b0 = *(const float4*)&Bs[k][tx * 4];
            float4 b1 = *(const float4*)&Bs[k][64 + tx * 4];
            float av[8] = {a0.x, a0.y, a0.z, a0.w, a1.x, a1.y, a1.z, a1.w};
            float bv[8] = {b0.x, b0.y, b0.z, b0.w, b1.x, b1.y, b1.z, b1.w};
            #pragma unroll
            for (int i = 0; i < 8; i++)
                #pragma unroll
                for (int j = 0; j < 8; j++)
                    acc[i][j] = fmaf(av[i], bv[j], acc[i][j]);
        }
        __syncthreads();
    }

    #pragma unroll
    for (int i = 0; i < 8; i++) {
        int r = m0 + ((i < 4) ? (ty * 4 + i) : (64 + ty * 4 + i - 4));
        #pragma unroll
        for (int jb = 0; jb < 2; jb++) {
            int c = n0 + jb * 64 + tx * 4;
            float4 v;
            v.x = acc[i][jb * 4 + 0];
            v.y = acc[i][jb * 4 + 1];
            v.z = acc[i][jb * 4 + 2];
            v.w = acc[i][jb * 4 + 3];
            if (BIAS) {
                float4 bb = *(const float4*)(bias + c);
                v.x += bb.x; v.y += bb.y; v.z += bb.z; v.w += bb.w;
            }
            if (RELU) {
                v.x = fmaxf(v.x, 0.0f); v.y = fmaxf(v.y, 0.0f);
                v.z = fmaxf(v.z, 0.0f); v.w = fmaxf(v.w, 0.0f);
            }
            if (RESID) {
                float4 rr = *(const float4*)(resid + (size_t)r * N + c);
                v.x += rr.x; v.y += rr.y; v.z += rr.z; v.w += rr.w;
            }
            *(float4*)(C + (size_t)r * N + c) = v;
        }
    }
}

// ============================================================
// fused causal attention with the reference's quirks:
//   scores[t,s] = (k[t] . q[s]) * E^-0.5 ,  v == q
// K,Q,O all in [B,T, H*HD] layout (head-major inner).
// grid: (T/8, B*H), 256 threads = 8 warps, warp = one query row.
// q-tiles (128 rows x 64) staged in SMEM, online softmax.
// ============================================================
__global__ __launch_bounds__(256) void attn_kernel(
    const float* __restrict__ K, const float* __restrict__ Q,
    float* __restrict__ O)
{
    __shared__ float qs[128][64];
    int bh = blockIdx.y;
    int b = bh >> 3, h = bh & 7;
    int wid = threadIdx.x >> 5, lane = threadIdx.x & 31;
    int t = blockIdx.x * 8 + wid;
    const float scale = 0.044194173824159216f;   // 512^-0.5 (E, not HD!)

    size_t kbase = ((size_t)(b * Tq + t)) * Eq + h * HDq;
    float k0 = K[kbase + lane] * scale;
    float k1 = K[kbase + lane + 32] * scale;

    float m = -1e30f, l = 0.0f, acc0 = 0.0f, acc1 = 0.0f;
    int tmax = blockIdx.x * 8 + 7;

    for (int s0 = 0; s0 <= tmax; s0 += 128) {
        // cooperative load of 128 q rows
        #pragma unroll
        for (int it = 0; it < 8; it++) {
            int idx = it * 256 + threadIdx.x;
            int r = idx >> 4, d4 = (idx & 15) * 4;
            *(float4*)&qs[r][d4] =
                *(const float4*)&Q[((size_t)(b * Tq + s0 + r)) * Eq + h * HDq + d4];
        }
        __syncthreads();

        int send = min(127, t - s0);
        for (int si = 0; si <= send; si++) {
            float q0 = qs[si][lane];
            float q1 = qs[si][lane + 32];
            float p = fmaf(k0, q0, k1 * q1);
            p += __shfl_xor_sync(0xffffffffu, p, 16);
            p += __shfl_xor_sync(0xffffffffu, p, 8);
            p += __shfl_xor_sync(0xffffffffu, p, 4);
            p += __shfl_xor_sync(0xffffffffu, p, 2);
            p += __shfl_xor_sync(0xffffffffu, p, 1);
            float mn = fmaxf(m, p);
            float alpha = __expf(m - mn);
            float w = __expf(p - mn);
            l    = fmaf(l,    alpha, w);
            acc0 = fmaf(acc0, alpha, w * q0);
            acc1 = fmaf(acc1, alpha, w * q1);
            m = mn;
        }
        __syncthreads();
    }
    float inv = 1.0f / l;
    O[kbase + lane]      = acc0 * inv;
    O[kbase + lane + 32] = acc1 * inv;
}

// ============================================================
// launch
// ============================================================
extern "C" void kernel_launch(void* const* d_in, const int* in_sizes, int n_in,
                              void* d_out, int out_size)
{
    const int*   x     = (const int*)  d_in[0];
    const float* tok   = (const float*)d_in[1];
    const float* pos   = (const float*)d_in[2];
    const float* Wk    = (const float*)d_in[3];
    const float* Wq    = (const float*)d_in[4];
    const float* Wres  = (const float*)d_in[5];
    const float* ln1g  = (const float*)d_in[6];
    const float* ln1b  = (const float*)d_in[7];
    const float* mlpW  = (const float*)d_in[8];
    const float* mlpb  = (const float*)d_in[9];
    const float* ln2g  = (const float*)d_in[10];
    const float* ln2b  = (const float*)d_in[11];
    const float* lnfg  = (const float*)d_in[12];
    const float* lnfb  = (const float*)d_in[13];
    const float* projW = (const float*)d_in[14];
    const float* projb = (const float*)d_in[15];
    float* out = (float*)d_out;

    float *h1, *h2, *hn, *kb, *qb, *mha, *wkr, *wqr;
    cudaGetSymbolAddress((void**)&h1,  g_h1);
    cudaGetSymbolAddress((void**)&h2,  g_h2);
    cudaGetSymbolAddress((void**)&hn,  g_hn);
    cudaGetSymbolAddress((void**)&kb,  g_k);
    cudaGetSymbolAddress((void**)&qb,  g_q);
    cudaGetSymbolAddress((void**)&mha, g_mha);
    cudaGetSymbolAddress((void**)&wkr, g_wkr);
    cudaGetSymbolAddress((void**)&wqr, g_wqr);

    repack_kernel<<<1280, 256>>>(Wk, wkr);
    repack_kernel<<<1280, 256>>>(Wq, wqr);
    embed_kernel<<<MROWS, 128>>>(x, tok, pos, h1);

    dim3 ge(Eq / 128, MROWS / 128);          // 4 x 32
    for (int i = 0; i < NBq; i++) {
        const size_t wo = (size_t)i * Eq * Eq;
        ln_kernel<<<MROWS, 128>>>(h1, ln1g + i * Eq, ln1b + i * Eq, hn);
        sgemm<false, false, false><<<ge, 256>>>(hn, wkr + wo, nullptr, nullptr, kb, MROWS, Eq, Eq);
        sgemm<false, false, false><<<ge, 256>>>(hn, wqr + wo, nullptr, nullptr, qb, MROWS, Eq, Eq);
        attn_kernel<<<dim3(Tq / 8, Bq * Hq), 256>>>(kb, qb, mha);
        sgemm<false, false, true><<<ge, 256>>>(h1, Wres + wo, nullptr, mha, h2, MROWS, Eq, Eq);
        ln_kernel<<<MROWS, 128>>>(h2, ln2g + i * Eq, ln2b + i * Eq, hn);
        sgemm<true, true, true><<<ge, 256>>>(hn, mlpW + wo, mlpb + i * Eq, h2, h1, MROWS, Eq, Eq);
    }

    ln_kernel<<<MROWS, 128>>>(h1, lnfg, lnfb, hn);
    sgemm<true, false, false><<<dim3(VOC / 128, MROWS / 128), 256>>>(
        hn, projW, projb, nullptr, out, MROWS, VOC, Eq);
}

// round 7
// speedup vs baseline: 1.4919x; 1.4919x over previous
#include <cuda_runtime.h>
#include <cuda_bf16.h>
#include <cstdint>

// ---- problem constants ----
#define Bq   4
#define Tq   1024
#define Eq   512
#define Hq   8
#define HDq  64
#define NBq  5
#define VOC  32000
#define MROWS (Bq*Tq)          // 4096

// ---- scratch (device globals; no allocations allowed) ----
__device__ float g_h1 [MROWS*Eq];
__device__ float g_h2 [MROWS*Eq];
__device__ float g_k  [MROWS*Eq];
__device__ float g_q  [MROWS*Eq];
__device__ float g_mha[MROWS*Eq];
__device__ float g_wkr[NBq*Eq*Eq];
__device__ float g_wqr[NBq*Eq*Eq];
// activation hi/lo splits (bf16)
__device__ __nv_bfloat16 g_h1hi[MROWS*Eq], g_h1lo[MROWS*Eq];
__device__ __nv_bfloat16 g_hnhi[MROWS*Eq], g_hnlo[MROWS*Eq];
// weight hi/lo splits, transposed to [N][K=512] row-major
__device__ __nv_bfloat16 g_wkhi[NBq*Eq*Eq], g_wklo[NBq*Eq*Eq];
__device__ __nv_bfloat16 g_wqhi[NBq*Eq*Eq], g_wqlo[NBq*Eq*Eq];
__device__ __nv_bfloat16 g_wrhi[NBq*Eq*Eq], g_wrlo[NBq*Eq*Eq];
__device__ __nv_bfloat16 g_wmhi[NBq*Eq*Eq], g_wmlo[NBq*Eq*Eq];
__device__ __nv_bfloat16 g_pjhi[(size_t)Eq*VOC], g_pjlo[(size_t)Eq*VOC];

// ============================================================
// helpers
// ============================================================
__device__ __forceinline__ uint32_t smem_u32(const void* p) {
    uint32_t a;
    asm("{ .reg .u64 t; cvta.to.shared.u64 t, %1; cvt.u32.u64 %0, t; }"
        : "=r"(a) : "l"(p));
    return a;
}
__device__ __forceinline__ void ldsm4(uint32_t* r, uint32_t addr) {
    asm volatile("ldmatrix.sync.aligned.m8n8.x4.shared.b16 {%0,%1,%2,%3}, [%4];"
                 : "=r"(r[0]), "=r"(r[1]), "=r"(r[2]), "=r"(r[3]) : "r"(addr));
}
__device__ __forceinline__ void mma16816(float* c, const uint32_t* a, const uint32_t* b) {
    asm volatile(
        "mma.sync.aligned.m16n8k16.row.col.f32.bf16.bf16.f32 "
        "{%0,%1,%2,%3}, {%4,%5,%6,%7}, {%8,%9}, {%0,%1,%2,%3};"
        : "+f"(c[0]), "+f"(c[1]), "+f"(c[2]), "+f"(c[3])
        : "r"(a[0]), "r"(a[1]), "r"(a[2]), "r"(a[3]), "r"(b[0]), "r"(b[1]));
}
#define CPASYNC(dst, src) \
    asm volatile("cp.async.cg.shared.global [%0], [%1], 16;" :: "r"(dst), "l"(src))
#define CPCOMMIT() asm volatile("cp.async.commit_group;" ::: "memory")
#define CPWAIT1()  asm volatile("cp.async.wait_group 1;" ::: "memory")
#define CPWAIT0()  asm volatile("cp.async.wait_group 0;" ::: "memory")

__device__ __forceinline__ uint32_t pack_hi2(float x, float y) {
    __nv_bfloat16 hx = __float2bfloat16(x), hy = __float2bfloat16(y);
    return (uint32_t)__bfloat16_as_ushort(hx) | ((uint32_t)__bfloat16_as_ushort(hy) << 16);
}
__device__ __forceinline__ uint32_t pack_lo2(float x, float y) {
    __nv_bfloat16 hx = __float2bfloat16(x), hy = __float2bfloat16(y);
    __nv_bfloat16 lx = __float2bfloat16(x - __bfloat162float(hx));
    __nv_bfloat16 ly = __float2bfloat16(y - __bfloat162float(hy));
    return (uint32_t)__bfloat16_as_ushort(lx) | ((uint32_t)__bfloat16_as_ushort(ly) << 16);
}

// ============================================================
// repack Wk/Wq: [NB,H,E,HD] -> [NB,E(k),H*HD(n)]
// ============================================================
__global__ void repack_kernel(const float* __restrict__ in, float* __restrict__ out)
{
    int tid = blockIdx.x * blockDim.x + threadIdx.x;
    if (tid >= NBq * Hq * Eq * 16) return;
    int o4 = tid & 15;
    int e  = (tid >> 4) & 511;
    int h  = (tid >> 13) & 7;
    int i  = tid >> 16;
    float4 v = *(const float4*)(in  + ((((size_t)i*Hq + h)*Eq + e)*HDq + o4*4));
    *(float4*)(out + (((size_t)i*Eq + e)*Eq + h*HDq + o4*4)) = v;
}

// ============================================================
// weight transpose + hi/lo split: W[K=512][Nfull] -> hi/lo [Nfull][512]
// grid (Nfull/32, 16, zCount), 256 threads, 32x32 tiles
// ============================================================
__global__ __launch_bounds__(256) void tsplit_kernel(
    const float* __restrict__ W, long long wChunk, int Nfull,
    __nv_bfloat16* __restrict__ hi, __nv_bfloat16* __restrict__ lo,
    long long oChunk)
{
    __shared__ float t[32][33];
    const float* w = W + (long long)blockIdx.z * wChunk;
    __nv_bfloat16* oh = hi + (long long)blockIdx.z * oChunk;
    __nv_bfloat16* ol = lo + (long long)blockIdx.z * oChunk;
    int n0 = blockIdx.x * 32, k0 = blockIdx.y * 32;
    int lw = threadIdx.x >> 5, lc = threadIdx.x & 31;
    #pragma unroll
    for (int i = 0; i < 4; i++) {
        int kk = lw + i * 8;
        t[kk][lc] = w[(size_t)(k0 + kk) * Nfull + n0 + lc];
    }
    __syncthreads();
    #pragma unroll
    for (int i = 0; i < 4; i++) {
        int nn = lw + i * 8;
        float v = t[lc][nn];
        __nv_bfloat16 h = __float2bfloat16(v);
        __nv_bfloat16 l = __float2bfloat16(v - __bfloat162float(h));
        size_t o = (size_t)(n0 + nn) * 512 + k0 + lc;
        oh[o] = h; ol[o] = l;
    }
}

// ============================================================
// embedding: h = tok_emb[x] + pos_emb ; also write hi/lo split
// ============================================================
__global__ void embed_kernel(const int* __restrict__ x,
                             const float* __restrict__ tok,
                             const float* __restrict__ pos,
                             float* __restrict__ h,
                             __nv_bfloat16* __restrict__ ohi,
                             __nv_bfloat16* __restrict__ olo)
{
    int row = blockIdx.x;
    int t   = row & (Tq - 1);
    int idx = x[row];
    int tid = threadIdx.x;
    float4 a = ((const float4*)(tok + (size_t)idx * Eq))[tid];
    float4 p = ((const float4*)(pos + (size_t)t   * Eq))[tid];
    float4 o; o.x = a.x+p.x; o.y = a.y+p.y; o.z = a.z+p.z; o.w = a.w+p.w;
    ((float4*)(h + (size_t)row * Eq))[tid] = o;
    size_t e = (size_t)row * Eq + tid * 4;
    *(uint2*)(ohi + e) = make_uint2(pack_hi2(o.x, o.y), pack_hi2(o.z, o.w));
    *(uint2*)(olo + e) = make_uint2(pack_lo2(o.x, o.y), pack_lo2(o.z, o.w));
}

// ============================================================
// layernorm -> hi/lo bf16 split (GEMM A operand format)
// ============================================================
__global__ void ln_split_kernel(const float* __restrict__ in,
                                const float* __restrict__ g,
                                const float* __restrict__ b,
                                __nv_bfloat16* __restrict__ ohi,
                                __nv_bfloat16* __restrict__ olo)
{
    int row = blockIdx.x, tid = threadIdx.x;
    float4 v = ((const float4*)(in + (size_t)row * Eq))[tid];
    float s  = v.x + v.y + v.z + v.w;
    float sq = v.x*v.x + v.y*v.y + v.z*v.z + v.w*v.w;
    #pragma unroll
    for (int o = 16; o; o >>= 1) {
        s  += __shfl_xor_sync(0xffffffffu, s,  o);
        sq += __shfl_xor_sync(0xffffffffu, sq, o);
    }
    __shared__ float sm1[4], sm2[4];
    int wid = tid >> 5, lane = tid & 31;
    if (lane == 0) { sm1[wid] = s; sm2[wid] = sq; }
    __syncthreads();
    s  = sm1[0] + sm1[1] + sm1[2] + sm1[3];
    sq = sm2[0] + sm2[1] + sm2[2] + sm2[3];
    float mu   = s * (1.0f / Eq);
    float var  = sq * (1.0f / Eq) - mu * mu;
    float rstd = rsqrtf(var + 1e-5f);
    float4 gv = ((const float4*)g)[tid];
    float4 bv = ((const float4*)b)[tid];
    float4 o;
    o.x = (v.x - mu) * rstd * gv.x + bv.x;
    o.y = (v.y - mu) * rstd * gv.y + bv.y;
    o.z = (v.z - mu) * rstd * gv.z + bv.z;
    o.w = (v.w - mu) * rstd * gv.w + bv.w;
    size_t e = (size_t)row * Eq + tid * 4;
    *(uint2*)(ohi + e) = make_uint2(pack_hi2(o.x, o.y), pack_hi2(o.z, o.w));
    *(uint2*)(olo + e) = make_uint2(pack_lo2(o.x, o.y), pack_lo2(o.z, o.w));
}

// ============================================================
// bf16x3 HMMA GEMM: C[M,N] = A[M,512] @ W[512,N]
// A given as hi/lo bf16 [M][512]; B as W^T hi/lo bf16 [N][512].
// acc += Ahi*Bhi + Ahi*Blo + Alo*Bhi  (fp32 accumulate)
// 128x128x32 tile, 256 thr = 8 warps (2m x 4n), warp 64x32,
// 2-stage cp.async double buffer, pitch-40 smem (ldmatrix conflict-free).
// ============================================================
#define PITCH 40
#define MATB  (128 * PITCH * 2)         // 10240 bytes per matrix tile
#define STAGEB (4 * MATB)               // 40960
#define SMEMB  (2 * STAGEB)             // 81920

template<bool BIAS, bool RELU, bool RESID, bool OSPLIT>
__global__ __launch_bounds__(256) void hgemm(
    const __nv_bfloat16* __restrict__ Ahi, const __nv_bfloat16* __restrict__ Alo,
    const __nv_bfloat16* __restrict__ Bhi, const __nv_bfloat16* __restrict__ Blo,
    const float* __restrict__ bias, const float* __restrict__ resid,
    float* __restrict__ C,
    __nv_bfloat16* __restrict__ Ohi, __nv_bfloat16* __restrict__ Olo,
    int N)
{
    extern __shared__ char dsm[];
    const uint32_t sb = smem_u32(dsm);
    const int tid = threadIdx.x;
    const int wid = tid >> 5, lane = tid & 31;
    const int wm = wid & 1, wn = wid >> 1;
    const int m0 = blockIdx.x * 128, n0 = blockIdx.y * 128;

    // fragment smem offsets (ldmatrix, per lane)
    uint32_t aOff[4], bOff[2];
    {
        int ml  = lane >> 3;                  // matrix index 0..3
        int r8  = lane & 7;
        int ar  = (ml & 1) * 8 + r8;
        int ac  = (ml >> 1) * 8;
        #pragma unroll
        for (int mi = 0; mi < 4; mi++)
            aOff[mi] = (uint32_t)(((wm * 64 + mi * 16 + ar) * PITCH + ac) * 2);
        int br  = (ml >> 1) * 8 + r8;
        int bc  = (ml & 1) * 8;
        #pragma unroll
        for (int j = 0; j < 2; j++)
            bOff[j] = (uint32_t)(((wn * 32 + j * 16 + br) * PITCH + bc) * 2);
    }

    auto loadStage = [&](int s) {
        int k0 = s * 32;
        uint32_t base = sb + (s & 1) * STAGEB;
        #pragma unroll
        for (int i = 0; i < 2; i++) {
            int idx = tid + i * 256;
            int row = idx >> 2, c4 = idx & 3;
            uint32_t doff = (uint32_t)((row * PITCH + c4 * 8) * 2);
            size_t ga = (size_t)(m0 + row) * 512 + k0 + c4 * 8;
            size_t gb = (size_t)(n0 + row) * 512 + k0 + c4 * 8;
            CPASYNC(base +            doff, Ahi + ga);
            CPASYNC(base + MATB     + doff, Alo + ga);
            CPASYNC(base + 2 * MATB + doff, Bhi + gb);
            CPASYNC(base + 3 * MATB + doff, Blo + gb);
        }
    };

    float acc[4][4][4];
    #pragma unroll
    for (int i = 0; i < 4; i++)
        #pragma unroll
        for (int j = 0; j < 4; j++)
            #pragma unroll
            for (int q = 0; q < 4; q++) acc[i][j][q] = 0.0f;

    loadStage(0); CPCOMMIT();

    for (int s = 0; s < 16; s++) {
        if (s < 15) { loadStage(s + 1); CPCOMMIT(); CPWAIT1(); }
        else        { CPWAIT0(); }
        __syncthreads();
        uint32_t base = sb + (s & 1) * STAGEB;
        #pragma unroll
        for (int kk = 0; kk < 2; kk++) {
            uint32_t ah[16], al[16], bh[8], bl[8];
            #pragma unroll
            for (int mi = 0; mi < 4; mi++) {
                ldsm4(ah + mi * 4, base +         aOff[mi] + kk * 32);
                ldsm4(al + mi * 4, base + MATB  + aOff[mi] + kk * 32);
            }
            #pragma unroll
            for (int j = 0; j < 2; j++) {
                ldsm4(bh + j * 4, base + 2 * MATB + bOff[j] + kk * 32);
                ldsm4(bl + j * 4, base + 3 * MATB + bOff[j] + kk * 32);
            }
            #pragma unroll
            for (int mi = 0; mi < 4; mi++)
                #pragma unroll
                for (int ni = 0; ni < 4; ni++) {
                    mma16816(acc[mi][ni], ah + mi * 4, bh + ni * 2);
                    mma16816(acc[mi][ni], ah + mi * 4, bl + ni * 2);
                    mma16816(acc[mi][ni], al + mi * 4, bh + ni * 2);
                }
        }
        __syncthreads();
    }

    // epilogue: d0,d1=(r,c..c+1), d2,d3=(r+8,c..c+1)
    const int r  = lane >> 2;
    const int cp = (lane & 3) * 2;
    #pragma unroll
    for (int mi = 0; mi < 4; mi++) {
        #pragma unroll
        for (int ni = 0; ni < 4; ni++) {
            int col  = n0 + wn * 32 + ni * 8 + cp;
            int row0 = m0 + wm * 64 + mi * 16 + r;
            #pragma unroll
            for (int hh = 0; hh < 2; hh++) {
                int row = row0 + hh * 8;
                float v0 = acc[mi][ni][hh * 2];
                float v1 = acc[mi][ni][hh * 2 + 1];
                if (BIAS) { v0 += bias[col]; v1 += bias[col + 1]; }
                if (RELU) { v0 = fmaxf(v0, 0.0f); v1 = fmaxf(v1, 0.0f); }
                if (RESID) {
                    float2 rr = *(const float2*)(resid + (size_t)row * N + col);
                    v0 += rr.x; v1 += rr.y;
                }
                *(float2*)(C + (size_t)row * N + col) = make_float2(v0, v1);
                if (OSPLIT) {
                    *(uint32_t*)(Ohi + (size_t)row * N + col) = pack_hi2(v0, v1);
                    *(uint32_t*)(Olo + (size_t)row * N + col) = pack_lo2(v0, v1);
                }
            }
        }
    }
}

// ============================================================
// fused causal attention (reference quirks: scores = k@q^T,
// v == q, scale = E^-0.5). 32 scores per lane per chunk.
// grid (T/8, B*H), 8 warps; warp = query row t.
// ============================================================
__global__ __launch_bounds__(256) void attn_kernel(
    const float* __restrict__ K, const float* __restrict__ Q,
    float* __restrict__ O)
{
    __shared__ float qs[128][69];                 // pad 69: conflict-free both ways
    int bh = blockIdx.y;
    int b = bh >> 3, h = bh & 7;
    int wid = threadIdx.x >> 5, lane = threadIdx.x & 31;
    int t = blockIdx.x * 8 + wid;
    const float scale = 0.044194173824159216f;    // 512^-0.5
    size_t kbase = ((size_t)(b * Tq + t)) * Eq + h * HDq;
    float k0 = K[kbase + lane] * scale;
    float k1 = K[kbase + lane + 32] * scale;
    float m = -1e30f, l = 0.0f, a0 = 0.0f, a1 = 0.0f;
    int tmax = blockIdx.x * 8 + 7;

    for (int s0 = 0; s0 <= tmax; s0 += 128) {
        #pragma unroll
        for (int it = 0; it < 8; it++) {
            int idx = it * 256 + threadIdx.x;
            int rr = idx >> 4, d4 = (idx & 15) * 4;
            float4 v = *(const float4*)&Q[((size_t)(b * Tq + s0 + rr)) * Eq + h * HDq + d4];
            qs[rr][d4] = v.x; qs[rr][d4+1] = v.y; qs[rr][d4+2] = v.z; qs[rr][d4+3] = v.w;
        }
        __syncthreads();

        int send = min(127, t - s0);
        int nch = (send >> 5) + 1;
        for (int c = 0; c < nch; c++) {
            int sb32 = c * 32;
            const float* qrow = qs[sb32 + lane];
            float p = 0.0f;
            #pragma unroll
            for (int d = 0; d < 32; d++)
                p = fmaf(__shfl_sync(0xffffffffu, k0, d), qrow[d], p);
            #pragma unroll
            for (int d = 0; d < 32; d++)
                p = fmaf(__shfl_sync(0xffffffffu, k1, d), qrow[d + 32], p);
            if (sb32 + lane > send) p = -1e30f;           // causal mask
            float cm = p;
            #pragma unroll
            for (int o = 16; o; o >>= 1)
                cm = fmaxf(cm, __shfl_xor_sync(0xffffffffu, cm, o));
            float mn = fmaxf(m, cm);
            float alpha = __expf(m - mn);
            float w = __expf(p - mn);
            float sw = w;
            #pragma unroll
            for (int o = 16; o; o >>= 1)
                sw += __shfl_xor_sync(0xffffffffu, sw, o);
            l = fmaf(l, alpha, sw);
            a0 *= alpha; a1 *= alpha;
            #pragma unroll 8
            for (int s2 = 0; s2 < 32; s2++) {
                float ws = __shfl_sync(0xffffffffu, w, s2);
                a0 = fmaf(ws, qs[sb32 + s2][lane], a0);
                a1 = fmaf(ws, qs[sb32 + s2][lane + 32], a1);
            }
            m = mn;
        }
        __syncthreads();
    }
    float inv = 1.0f / l;
    O[kbase + lane]      = a0 * inv;
    O[kbase + lane + 32] = a1 * inv;
}

// ============================================================
// launch
// ============================================================
extern "C" void kernel_launch(void* const* d_in, const int* in_sizes, int n_in,
                              void* d_out, int out_size)
{
    const int*   x     = (const int*)  d_in[0];
    const float* tok   = (const float*)d_in[1];
    const float* pos   = (const float*)d_in[2];
    const float* Wk    = (const float*)d_in[3];
    const float* Wq    = (const float*)d_in[4];
    const float* Wres  = (const float*)d_in[5];
    const float* ln1g  = (const float*)d_in[6];
    const float* ln1b  = (const float*)d_in[7];
    const float* mlpW  = (const float*)d_in[8];
    const float* mlpb  = (const float*)d_in[9];
    const float* ln2g  = (const float*)d_in[10];
    const float* ln2b  = (const float*)d_in[11];
    const float* lnfg  = (const float*)d_in[12];
    const float* lnfb  = (const float*)d_in[13];
    const float* projW = (const float*)d_in[14];
    const float* projb = (const float*)d_in[15];
    float* out = (float*)d_out;

    float *h1, *h2, *kb, *qb, *mha, *wkr, *wqr;
    __nv_bfloat16 *h1hi, *h1lo, *hnhi, *hnlo;
    __nv_bfloat16 *wkhi, *wklo, *wqhi, *wqlo, *wrhi, *wrlo, *wmhi, *wmlo, *pjhi, *pjlo;
    cudaGetSymbolAddress((void**)&h1,  g_h1);
    cudaGetSymbolAddress((void**)&h2,  g_h2);
    cudaGetSymbolAddress((void**)&kb,  g_k);
    cudaGetSymbolAddress((void**)&qb,  g_q);
    cudaGetSymbolAddress((void**)&mha, g_mha);
    cudaGetSymbolAddress((void**)&wkr, g_wkr);
    cudaGetSymbolAddress((void**)&wqr, g_wqr);
    cudaGetSymbolAddress((void**)&h1hi, g_h1hi);
    cudaGetSymbolAddress((void**)&h1lo, g_h1lo);
    cudaGetSymbolAddress((void**)&hnhi, g_hnhi);
    cudaGetSymbolAddress((void**)&hnlo, g_hnlo);
    cudaGetSymbolAddress((void**)&wkhi, g_wkhi);
    cudaGetSymbolAddress((void**)&wklo, g_wklo);
    cudaGetSymbolAddress((void**)&wqhi, g_wqhi);
    cudaGetSymbolAddress((void**)&wqlo, g_wqlo);
    cudaGetSymbolAddress((void**)&wrhi, g_wrhi);
    cudaGetSymbolAddress((void**)&wrlo, g_wrlo);
    cudaGetSymbolAddress((void**)&wmhi, g_wmhi);
    cudaGetSymbolAddress((void**)&wmlo, g_wmlo);
    cudaGetSymbolAddress((void**)&pjhi, g_pjhi);
    cudaGetSymbolAddress((void**)&pjlo, g_pjlo);

    cudaFuncSetAttribute(hgemm<false,false,false,false>, cudaFuncAttributeMaxDynamicSharedMemorySize, SMEMB);
    cudaFuncSetAttribute(hgemm<false,false,true,false>,  cudaFuncAttributeMaxDynamicSharedMemorySize, SMEMB);
    cudaFuncSetAttribute(hgemm<true,true,true,true>,     cudaFuncAttributeMaxDynamicSharedMemorySize, SMEMB);
    cudaFuncSetAttribute(hgemm<true,false,false,false>,  cudaFuncAttributeMaxDynamicSharedMemorySize, SMEMB);

    // ---- weight prep ----
    repack_kernel<<<1280, 256>>>(Wk, wkr);
    repack_kernel<<<1280, 256>>>(Wq, wqr);
    const long long EC = (long long)Eq * Eq;
    tsplit_kernel<<<dim3(16, 16, NBq), 256>>>(wkr,  EC, Eq,  wkhi, wklo, EC);
    tsplit_kernel<<<dim3(16, 16, NBq), 256>>>(wqr,  EC, Eq,  wqhi, wqlo, EC);
    tsplit_kernel<<<dim3(16, 16, NBq), 256>>>(Wres, EC, Eq,  wrhi, wrlo, EC);
    tsplit_kernel<<<dim3(16, 16, NBq), 256>>>(mlpW, EC, Eq,  wmhi, wmlo, EC);
    tsplit_kernel<<<dim3(1000, 16, 1), 256>>>(projW, 0, VOC, pjhi, pjlo, 0);

    embed_kernel<<<MROWS, 128>>>(x, tok, pos, h1, h1hi, h1lo);

    dim3 ge(MROWS / 128, Eq / 128);              // 32 x 4
    for (int i = 0; i < NBq; i++) {
        const size_t wo = (size_t)i * Eq * Eq;
        ln_split_kernel<<<MROWS, 128>>>(h1, ln1g + i * Eq, ln1b + i * Eq, hnhi, hnlo);
        hgemm<false,false,false,false><<<ge, 256, SMEMB>>>(
            hnhi, hnlo, wkhi + wo, wklo + wo, nullptr, nullptr, kb, nullptr, nullptr, Eq);
        hgemm<false,false,false,false><<<ge, 256, SMEMB>>>(
            hnhi, hnlo, wqhi + wo, wqlo + wo, nullptr, nullptr, qb, nullptr, nullptr, Eq);
        attn_kernel<<<dim3(Tq / 8, Bq * Hq), 256>>>(kb, qb, mha);
        hgemm<false,false,true,false><<<ge, 256, SMEMB>>>(
            h1hi, h1lo, wrhi + wo, wrlo + wo, nullptr, mha, h2, nullptr, nullptr, Eq);
        ln_split_kernel<<<MROWS, 128>>>(h2, ln2g + i * Eq, ln2b + i * Eq, hnhi, hnlo);
        hgemm<true,true,true,true><<<ge, 256, SMEMB>>>(
            hnhi, hnlo, wmhi + wo, wmlo + wo, mlpb + i * Eq, h2, h1, h1hi, h1lo, Eq);
    }

    ln_split_kernel<<<MROWS, 128>>>(h1, lnfg, lnfb, hnhi, hnlo);
    hgemm<true,false,false,false><<<dim3(MROWS / 128, VOC / 128), 256, SMEMB>>>(
        hnhi, hnlo, pjhi, pjlo, projb, nullptr, out, nullptr, nullptr, VOC);
}